// round 4
// baseline (speedup 1.0000x reference)
#include <cuda_runtime.h>
#include <cstdint>
#include <math.h>

typedef unsigned long long ull;

#define NB 32
#define NS 512
#define NE 300
#define NHH 256
#define NT 12
#define NGATE 1024
#define TAG_START 10
#define TAG_STOP 11
#define FNEG (-10000.0f)

// ---------------- scratch (static device arrays; no allocation) ----------------
static __device__ float g_gates[2u * NS * NB * NGATE];    // [dir][m=s*32+b][1024]
static __device__ float g_hx[2u * NS * 64 * 128];         // chunk-major: [dir][s][cta][b][4]
static __device__ float g_feat[(size_t)NB * NS * NT];     // [b][s][12]
static __device__ int   g_flags[2u * NS * 64 * 8];        // [dir][s][cta] stride-8 (32B spread)

__device__ __forceinline__ float sigf(float x) { return 1.f / (1.f + __expf(-x)); }

__device__ __forceinline__ ull pack2(float lo, float hi) {
    ull r; asm("mov.b64 %0, {%1, %2};" : "=l"(r) : "f"(lo), "f"(hi)); return r;
}
__device__ __forceinline__ float2 unpack2(ull v) {
    float2 f; asm("mov.b64 {%0, %1}, %2;" : "=f"(f.x), "=f"(f.y) : "l"(v)); return f;
}
__device__ __forceinline__ void ffma2(ull& d, ull a, ull b) {
    asm("fma.rn.f32x2 %0, %1, %2, %0;" : "+l"(d) : "l"(a), "l"(b));
}
__device__ __forceinline__ void st_release_gpu(int* p, int v) {
    asm volatile("st.release.gpu.global.b32 [%0], %1;" :: "l"(p), "r"(v) : "memory");
}
__device__ __forceinline__ int ld_acquire_gpu(const int* p) {
    int v; asm volatile("ld.acquire.gpu.global.b32 %0, [%1];" : "=r"(v) : "l"(p) : "memory");
    return v;
}

// ---------------- zero the flags (runs first each replay) ----------------
__global__ void zero_flags_kernel() {
    int4* p = (int4*)g_flags;
    const int n = (2 * NS * 64 * 8) / 4;
    for (int i = blockIdx.x * blockDim.x + threadIdx.x; i < n; i += gridDim.x * blockDim.x)
        p[i] = make_int4(0, 0, 0, 0);
}

// ---------------- Phase A: embedding gather + input GEMM (f32x2) ----------------
// BM=128, BN=64, BK=20. 256 threads, 8x4 microtile, k-paired accumulators. (round-2 version)
__global__ void __launch_bounds__(256)
input_gemm_kernel(const int* __restrict__ inputs,
                  const float* __restrict__ embed,
                  const float* __restrict__ wih_f,
                  const float* __restrict__ bih_f,
                  const float* __restrict__ bhh_f,
                  const float* __restrict__ wih_b,
                  const float* __restrict__ bih_b,
                  const float* __restrict__ bhh_b) {
    const int dir = blockIdx.z;
    const float* __restrict__ wih = dir ? wih_b : wih_f;
    const float* __restrict__ bih = dir ? bih_b : bih_f;
    const float* __restrict__ bhh = dir ? bhh_b : bhh_f;
    const int n0 = blockIdx.x * 64;
    const int m0 = blockIdx.y * 128;

    __shared__ int    tok_s[128];
    __shared__ float2 A_s[10 * 128];   // [kp][m] pairs (even k, odd k)
    __shared__ float2 W_s[10 * 64];    // [kp][n]

    const int tid = threadIdx.x;
    if (tid < 128) {
        const int m = m0 + tid;
        tok_s[tid] = inputs[(m & 31) * NS + (m >> 5)];
    }
    const int tn = tid & 15;
    const int tm = tid >> 4;

    ull acc[8][4];
#pragma unroll
    for (int i = 0; i < 8; i++)
#pragma unroll
        for (int j = 0; j < 4; j++) acc[i][j] = 0ull;

    __syncthreads();
    for (int kt = 0; kt < 15; kt++) {
        const int k0 = kt * 20;
        __syncthreads();
        for (int u = tid; u < 960; u += 256) {
            if (u < 640) {
                const int row = u / 5, c4 = u % 5;
                const float4 v = *(const float4*)(embed + (size_t)tok_s[row] * NE + k0 + c4 * 4);
                A_s[(c4 * 2) * 128 + row]     = make_float2(v.x, v.y);
                A_s[(c4 * 2 + 1) * 128 + row] = make_float2(v.z, v.w);
            } else {
                const int idx = u - 640;
                const int n = idx / 5, c4 = idx % 5;
                const float4 v = *(const float4*)(wih + (size_t)(n0 + n) * NE + k0 + c4 * 4);
                W_s[(c4 * 2) * 64 + n]     = make_float2(v.x, v.y);
                W_s[(c4 * 2 + 1) * 64 + n] = make_float2(v.z, v.w);
            }
        }
        __syncthreads();
#pragma unroll
        for (int kp = 0; kp < 10; kp++) {
            const ulonglong2* ap = (const ulonglong2*)(A_s + kp * 128 + tm * 8);
            const ulonglong2* wp = (const ulonglong2*)(W_s + kp * 64 + tn * 4);
            const ulonglong2 a0 = ap[0], a1 = ap[1], a2 = ap[2], a3 = ap[3];
            const ulonglong2 w0 = wp[0], w1 = wp[1];
            const ull a[8] = {a0.x, a0.y, a1.x, a1.y, a2.x, a2.y, a3.x, a3.y};
            const ull w[4] = {w0.x, w0.y, w1.x, w1.y};
#pragma unroll
            for (int i = 0; i < 8; i++)
#pragma unroll
                for (int j = 0; j < 4; j++) ffma2(acc[i][j], a[i], w[j]);
        }
    }

    const int ncol = n0 + tn * 4;
    const float4 b1 = *(const float4*)(bih + ncol);
    const float4 b2 = *(const float4*)(bhh + ncol);
    const float bx = b1.x + b2.x, by = b1.y + b2.y, bz = b1.z + b2.z, bw = b1.w + b2.w;
#pragma unroll
    for (int i = 0; i < 8; i++) {
        const int m = m0 + tm * 8 + i;
        const float2 s0 = unpack2(acc[i][0]);
        const float2 s1 = unpack2(acc[i][1]);
        const float2 s2 = unpack2(acc[i][2]);
        const float2 s3 = unpack2(acc[i][3]);
        const float4 o = make_float4(s0.x + s0.y + bx, s1.x + s1.y + by,
                                     s2.x + s2.y + bz, s3.x + s3.y + bw);
        *(float4*)(g_gates + ((size_t)dir * (NS * NB) + m) * NGATE + ncol) = o;
    }
}

// ---------------- Phase B: persistent bidirectional LSTM recurrence ----------------
// 128 CTAs (dir = bx>>6, cta = bx&63), 128 threads. CTA owns hidden units [cta*4, cta*4+4).
// Thread = (b = tid>>2, jj = tid&3) owns all 4 gates of unit j0+jj for batch b: no reduction.
// h exchange chunk-major; per-chunk poll+stage overlaps the straggler wait.
__global__ void lstm_rec_kernel(const float* __restrict__ whh_f,
                                const float* __restrict__ whh_b) {
    extern __shared__ char smraw[];
    ull*   w2_s = (ull*)smraw;              // [kp=128][jj=4][g=4] = 16KB
    float* h_s  = (float*)(smraw + 16384);  // chunk-major [c=64][b=32][4] = 32KB

    const int tid = threadIdx.x;
    const int dir = blockIdx.x >> 6;
    const int cta = blockIdx.x & 63;
    const int j0 = cta * 4;
    const float* __restrict__ whh = dir ? whh_b : whh_f;

    // weights: w2_s[kp*16 + jj*4 + g] = pack(whh[g*256+j0+jj][2kp], [2kp+1])
    for (int idx = tid; idx < 2048; idx += 128) {
        const int kp = idx >> 4, r = idx & 15;
        const int jjw = r >> 2, gw = r & 3;
        const float2 wv = *(const float2*)(whh + (size_t)((gw << 8) + j0 + jjw) * NHH + kp * 2);
        w2_s[idx] = pack2(wv.x, wv.y);
    }

    const int b  = tid >> 2;
    const int jj = tid & 3;
    const int mc = tid >> 1;    // my staging chunk
    const int mh = tid & 1;     // half of the chunk
    float c_reg = 0.f;
    int* const flag_dir = g_flags + dir * (NS * 64 * 8);
    const size_t hx_dir = (size_t)dir * NS * 64 * 128;
    const float* const gdir = g_gates + (size_t)dir * (NS * NB * NGATE) + j0 + jj;

    // prefetch gates for t=0
    float n_i, n_f, n_g, n_o;
    {
        const int s0 = dir ? (NS - 1) : 0;
        const float* gp = gdir + ((size_t)s0 * NB + b) * NGATE;
        n_i = __ldcg(gp); n_f = __ldcg(gp + 256); n_g = __ldcg(gp + 512); n_o = __ldcg(gp + 768);
    }
    __syncthreads();

    for (int t = 0; t < NS; t++) {
        const int s = dir ? (NS - 1 - t) : t;
        float a_i = n_i, a_f = n_f, a_g = n_g, a_o = n_o;
        // prefetch gates for t+1 (hide DRAM latency/jitter behind this step)
        if (t + 1 < NS) {
            const int sn = dir ? (s - 1) : (s + 1);
            const float* gp = gdir + ((size_t)sn * NB + b) * NGATE;
            n_i = __ldcg(gp); n_f = __ldcg(gp + 256); n_g = __ldcg(gp + 512); n_o = __ldcg(gp + 768);
        }

        if (t > 0) {
            const int sp = dir ? (s + 1) : (s - 1);
            // per-chunk poll + stage (overlaps straggler wait)
            {
                const int* fp = flag_dir + sp * (64 * 8) + mc * 8;
                while (ld_acquire_gpu(fp) == 0) {}
                const float4* src = (const float4*)(g_hx + hx_dir + ((size_t)sp * 64 + mc) * 128) + mh * 16;
                float4* dst = (float4*)(h_s + mc * 128) + mh * 16;
#pragma unroll
                for (int q = 0; q < 16; q++) dst[q] = __ldcg(src + q);
            }
            __syncthreads();

            ull acc0 = 0, acc1 = 0, acc2 = 0, acc3 = 0;
#pragma unroll 4
            for (int c = 0; c < 64; c++) {
                const ulonglong2 hv = *(const ulonglong2*)(h_s + c * 128 + b * 4);
                const ulonglong2 wa = *(const ulonglong2*)(w2_s + (2 * c) * 16 + jj * 4);
                const ulonglong2 wb = *(const ulonglong2*)(w2_s + (2 * c) * 16 + jj * 4 + 2);
                const ulonglong2 wc = *(const ulonglong2*)(w2_s + (2 * c + 1) * 16 + jj * 4);
                const ulonglong2 wd = *(const ulonglong2*)(w2_s + (2 * c + 1) * 16 + jj * 4 + 2);
                ffma2(acc0, hv.x, wa.x); ffma2(acc1, hv.x, wa.y);
                ffma2(acc2, hv.x, wb.x); ffma2(acc3, hv.x, wb.y);
                ffma2(acc0, hv.y, wc.x); ffma2(acc1, hv.y, wc.y);
                ffma2(acc2, hv.y, wd.x); ffma2(acc3, hv.y, wd.y);
            }
            const float2 r0 = unpack2(acc0), r1 = unpack2(acc1);
            const float2 r2 = unpack2(acc2), r3 = unpack2(acc3);
            a_i += r0.x + r0.y; a_f += r1.x + r1.y;
            a_g += r2.x + r2.y; a_o += r3.x + r3.y;
        }

        const float ig = sigf(a_i), fg = sigf(a_f), og = sigf(a_o);
        const float tg = 2.f * sigf(2.f * a_g) - 1.f;             // tanh
        const float cn = fg * c_reg + ig * tg;
        const float hn = og * (2.f * sigf(2.f * cn) - 1.f);
        c_reg = cn;
        __stcg(g_hx + hx_dir + ((size_t)s * 64 + cta) * 128 + tid, hn);  // coalesced 128B/warp
        __syncthreads();
        if (tid == 0) st_release_gpu(flag_dir + s * (64 * 8) + cta * 8, 1);
    }
}

// ---------------- Phase C1: feats = hs @ fc_w^T + fc_b (reads chunk-major g_hx) ----------------
__global__ void feats_kernel(const float* __restrict__ fc_w,
                             const float* __restrict__ fc_b) {
    __shared__ float fcw_s[NT * 512];
    __shared__ float fcb_s[NT];
    const int s = blockIdx.x;
    const int tid = threadIdx.x;
    for (int i = tid; i < NT * 512; i += 256) fcw_s[i] = fc_w[i];
    if (tid < NT) fcb_s[tid] = fc_b[tid];
    __syncthreads();

    const int w = tid >> 5, lane = tid & 31;
    const float* base_f = g_hx + (size_t)s * 64 * 128;                       // dir 0
    const float* base_b = g_hx + ((size_t)NS + s) * 64 * 128;                // dir 1
#pragma unroll
    for (int rep = 0; rep < 4; rep++) {
        const int b = w + rep * 8;
        const float4 v0 = __ldcg((const float4*)(base_f + (size_t)lane * 128 + b * 4));
        const float4 v1 = __ldcg((const float4*)(base_f + (size_t)(lane + 32) * 128 + b * 4));
        const float4 v2 = __ldcg((const float4*)(base_b + (size_t)lane * 128 + b * 4));
        const float4 v3 = __ldcg((const float4*)(base_b + (size_t)(lane + 32) * 128 + b * 4));
#pragma unroll
        for (int tt = 0; tt < NT; tt++) {
            const float4* wr = (const float4*)(fcw_s + tt * 512);
            const float4 w0 = wr[lane];
            const float4 w1 = wr[lane + 32];
            const float4 w2 = wr[lane + 64];
            const float4 w3 = wr[lane + 96];
            float p = v0.x * w0.x + v0.y * w0.y + v0.z * w0.z + v0.w * w0.w
                    + v1.x * w1.x + v1.y * w1.y + v1.z * w1.z + v1.w * w1.w
                    + v2.x * w2.x + v2.y * w2.y + v2.z * w2.z + v2.w * w2.w
                    + v3.x * w3.x + v3.y * w3.y + v3.z * w3.z + v3.w * w3.w;
            p += __shfl_xor_sync(0xffffffffu, p, 16);
            p += __shfl_xor_sync(0xffffffffu, p, 8);
            p += __shfl_xor_sync(0xffffffffu, p, 4);
            p += __shfl_xor_sync(0xffffffffu, p, 2);
            p += __shfl_xor_sync(0xffffffffu, p, 1);
            if (lane == 0) g_feat[((size_t)b * NS + s) * NT + tt] = p + fcb_s[tt];
        }
    }
}

// ---------------- Phase C2: Viterbi, one warp per batch ----------------
__global__ void viterbi_kernel(const float* __restrict__ trans,
                               float* __restrict__ out, int out_size) {
    __shared__ float feat_s[NS * NT];
    __shared__ unsigned char bp_s[NS * NT];
    __shared__ float term_s[NT];
    const int b = blockIdx.x;
    const int lane = threadIdx.x;  // 32

    const float4* src = (const float4*)(g_feat + (size_t)b * NS * NT);
    float4* dst = (float4*)feat_s;
    for (int i = lane; i < (NS * NT) / 4; i += 32) dst[i] = __ldcg(src + i);

    const int tl = (lane < NT) ? lane : (NT - 1);
    float tr_reg[NT];
#pragma unroll
    for (int p = 0; p < NT; p++) tr_reg[p] = trans[p * NT + tl];
    const float tr_stop = trans[tl * NT + TAG_STOP];
    __syncwarp();

    float v = (lane == TAG_START) ? 0.f : FNEG;
    for (int s = 0; s < NS; s++) {
        float best = -3.0e38f;
        int bpi = 0;
#pragma unroll
        for (int p = 0; p < NT; p++) {
            const float sc = __shfl_sync(0xffffffffu, v, p) + tr_reg[p];
            if (sc > best) { best = sc; bpi = p; }
        }
        v = best + feat_s[s * NT + tl];
        if (lane < NT) bp_s[s * NT + lane] = (unsigned char)bpi;
    }
    if (lane < NT) term_s[lane] = v + tr_stop;
    __syncwarp();
    if (lane == 0) {
        float best = term_s[0];
        int last = 0;
#pragma unroll
        for (int tt = 1; tt < NT; tt++)
            if (term_s[tt] > best) { best = term_s[tt]; last = tt; }
        if (b < out_size) out[b] = best;
        const int base = NB + b * NS;
        if (base + NS - 1 < out_size) out[base + NS - 1] = (float)last;
        int tag = last;
        for (int s = NS - 1; s >= 0; s--) {
            const int pv = bp_s[s * NT + tag];
            if (s >= 1 && base + s - 1 < out_size) out[base + s - 1] = (float)pv;
            tag = pv;
        }
    }
}

// ---------------- launch ----------------
extern "C" void kernel_launch(void* const* d_in, const int* in_sizes, int n_in,
                              void* d_out, int out_size) {
    const int*   inputs = (const int*)d_in[0];
    const float* embed  = (const float*)d_in[1];
    const float* wih_f  = (const float*)d_in[2];
    const float* whh_f  = (const float*)d_in[3];
    const float* bih_f  = (const float*)d_in[4];
    const float* bhh_f  = (const float*)d_in[5];
    const float* wih_b  = (const float*)d_in[6];
    const float* whh_b  = (const float*)d_in[7];
    const float* bih_b  = (const float*)d_in[8];
    const float* bhh_b  = (const float*)d_in[9];
    const float* fc_w   = (const float*)d_in[10];
    const float* fc_b   = (const float*)d_in[11];
    const float* trans  = (const float*)d_in[12];

    const int lstm_smem = 16384 + 32768;   // 48KB
    cudaFuncSetAttribute(lstm_rec_kernel, cudaFuncAttributeMaxDynamicSharedMemorySize, lstm_smem);

    zero_flags_kernel<<<256, 256>>>();
    input_gemm_kernel<<<dim3(16, 128, 2), 256>>>(inputs, embed,
                                                 wih_f, bih_f, bhh_f,
                                                 wih_b, bih_b, bhh_b);
    lstm_rec_kernel<<<128, 128, lstm_smem>>>(whh_f, whh_b);
    feats_kernel<<<NS, 256>>>(fc_w, fc_b);
    viterbi_kernel<<<NB, 32>>>(trans, (float*)d_out, out_size);
}

// round 5
// speedup vs baseline: 1.0058x; 1.0058x over previous
#include <cuda_runtime.h>
#include <cstdint>
#include <math.h>

typedef unsigned long long ull;

#define NB 32
#define NS 512
#define NE 300
#define NHH 256
#define NT 12
#define NGATE 1024
#define TAG_START 10
#define TAG_STOP 11
#define FNEG (-10000.0f)

// ---------------- scratch (static device arrays; no allocation) ----------------
static __device__ float g_gates[2u * NS * NB * NGATE];    // [dir][m=s*32+b][1024]
static __device__ float g_hx[2u * NS * 64 * 128];         // chunk-major: [dir][s][cta][b][4]
static __device__ float g_feat[(size_t)NB * NS * NT];     // [b][s][12]
static __device__ int   g_flags[2u * NS * 64 * 8];        // producer flags [dir][s][cta] stride-8
static __device__ int   g_round[2u * NS * 8];             // aggregated round flags [dir][s] stride-8

__device__ __forceinline__ float sigf(float x) { return 1.f / (1.f + __expf(-x)); }

__device__ __forceinline__ ull pack2(float lo, float hi) {
    ull r; asm("mov.b64 %0, {%1, %2};" : "=l"(r) : "f"(lo), "f"(hi)); return r;
}
__device__ __forceinline__ float2 unpack2(ull v) {
    float2 f; asm("mov.b64 {%0, %1}, %2;" : "=f"(f.x), "=f"(f.y) : "l"(v)); return f;
}
__device__ __forceinline__ void ffma2(ull& d, ull a, ull b) {
    asm("fma.rn.f32x2 %0, %1, %2, %0;" : "+l"(d) : "l"(a), "l"(b));
}
__device__ __forceinline__ void st_release_gpu(int* p, int v) {
    asm volatile("st.release.gpu.global.b32 [%0], %1;" :: "l"(p), "r"(v) : "memory");
}
__device__ __forceinline__ int ld_acquire_gpu(const int* p) {
    int v; asm volatile("ld.acquire.gpu.global.b32 %0, [%1];" : "=r"(v) : "l"(p) : "memory");
    return v;
}

// ---------------- zero the flags (runs first each replay) ----------------
__global__ void zero_flags_kernel() {
    const int n1 = 2 * NS * 64 * 8;
    const int n2 = 2 * NS * 8;
    for (int i = blockIdx.x * blockDim.x + threadIdx.x; i < n1 + n2; i += gridDim.x * blockDim.x) {
        if (i < n1) g_flags[i] = 0;
        else        g_round[i - n1] = 0;
    }
}

// ---------------- Phase A: embedding gather + input GEMM (f32x2) ----------------
// BM=128, BN=64, BK=20. 256 threads, 8x4 microtile, k-paired accumulators. (round-2 version)
__global__ void __launch_bounds__(256)
input_gemm_kernel(const int* __restrict__ inputs,
                  const float* __restrict__ embed,
                  const float* __restrict__ wih_f,
                  const float* __restrict__ bih_f,
                  const float* __restrict__ bhh_f,
                  const float* __restrict__ wih_b,
                  const float* __restrict__ bih_b,
                  const float* __restrict__ bhh_b) {
    const int dir = blockIdx.z;
    const float* __restrict__ wih = dir ? wih_b : wih_f;
    const float* __restrict__ bih = dir ? bih_b : bih_f;
    const float* __restrict__ bhh = dir ? bhh_b : bhh_f;
    const int n0 = blockIdx.x * 64;
    const int m0 = blockIdx.y * 128;

    __shared__ int    tok_s[128];
    __shared__ float2 A_s[10 * 128];   // [kp][m] pairs (even k, odd k)
    __shared__ float2 W_s[10 * 64];    // [kp][n]

    const int tid = threadIdx.x;
    if (tid < 128) {
        const int m = m0 + tid;
        tok_s[tid] = inputs[(m & 31) * NS + (m >> 5)];
    }
    const int tn = tid & 15;
    const int tm = tid >> 4;

    ull acc[8][4];
#pragma unroll
    for (int i = 0; i < 8; i++)
#pragma unroll
        for (int j = 0; j < 4; j++) acc[i][j] = 0ull;

    __syncthreads();
    for (int kt = 0; kt < 15; kt++) {
        const int k0 = kt * 20;
        __syncthreads();
        for (int u = tid; u < 960; u += 256) {
            if (u < 640) {
                const int row = u / 5, c4 = u % 5;
                const float4 v = *(const float4*)(embed + (size_t)tok_s[row] * NE + k0 + c4 * 4);
                A_s[(c4 * 2) * 128 + row]     = make_float2(v.x, v.y);
                A_s[(c4 * 2 + 1) * 128 + row] = make_float2(v.z, v.w);
            } else {
                const int idx = u - 640;
                const int n = idx / 5, c4 = idx % 5;
                const float4 v = *(const float4*)(wih + (size_t)(n0 + n) * NE + k0 + c4 * 4);
                W_s[(c4 * 2) * 64 + n]     = make_float2(v.x, v.y);
                W_s[(c4 * 2 + 1) * 64 + n] = make_float2(v.z, v.w);
            }
        }
        __syncthreads();
#pragma unroll
        for (int kp = 0; kp < 10; kp++) {
            const ulonglong2* ap = (const ulonglong2*)(A_s + kp * 128 + tm * 8);
            const ulonglong2* wp = (const ulonglong2*)(W_s + kp * 64 + tn * 4);
            const ulonglong2 a0 = ap[0], a1 = ap[1], a2 = ap[2], a3 = ap[3];
            const ulonglong2 w0 = wp[0], w1 = wp[1];
            const ull a[8] = {a0.x, a0.y, a1.x, a1.y, a2.x, a2.y, a3.x, a3.y};
            const ull w[4] = {w0.x, w0.y, w1.x, w1.y};
#pragma unroll
            for (int i = 0; i < 8; i++)
#pragma unroll
                for (int j = 0; j < 4; j++) ffma2(acc[i][j], a[i], w[j]);
        }
    }

    const int ncol = n0 + tn * 4;
    const float4 b1 = *(const float4*)(bih + ncol);
    const float4 b2 = *(const float4*)(bhh + ncol);
    const float bx = b1.x + b2.x, by = b1.y + b2.y, bz = b1.z + b2.z, bw = b1.w + b2.w;
#pragma unroll
    for (int i = 0; i < 8; i++) {
        const int m = m0 + tm * 8 + i;
        const float2 s0 = unpack2(acc[i][0]);
        const float2 s1 = unpack2(acc[i][1]);
        const float2 s2 = unpack2(acc[i][2]);
        const float2 s3 = unpack2(acc[i][3]);
        const float4 o = make_float4(s0.x + s0.y + bx, s1.x + s1.y + by,
                                     s2.x + s2.y + bz, s3.x + s3.y + bw);
        *(float4*)(g_gates + ((size_t)dir * (NS * NB) + m) * NGATE + ncol) = o;
    }
}

// ---------------- Phase B: persistent bidirectional LSTM recurrence ----------------
// 128 CTAs (dir = bx>>6, cta = bx&63), 128 threads. CTA owns hidden units [cta*4, cta*4+4).
// Thread = (b, jj) owns all 4 gates of its unit: no cross-thread reduction.
// Sync: producers st.release spread flags; CTA 0 per dir aggregates into one round flag;
// all other CTAs spin one thread on that single flag. Bulk coalesced 32KB h stage.
__global__ void lstm_rec_kernel(const float* __restrict__ whh_f,
                                const float* __restrict__ whh_b) {
    extern __shared__ char smraw[];
    ull*   w2_s = (ull*)smraw;              // [kp=128][jj=4][g=4] = 16KB
    float* h_s  = (float*)(smraw + 16384);  // chunk-major [c=64][b=32][4] = 32KB

    const int tid = threadIdx.x;
    const int dir = blockIdx.x >> 6;
    const int cta = blockIdx.x & 63;
    const int j0 = cta * 4;
    const float* __restrict__ whh = dir ? whh_b : whh_f;

    // weights: w2_s[kp*16 + jj*4 + g] = pack(whh[g*256+j0+jj][2kp], [2kp+1])
    for (int idx = tid; idx < 2048; idx += 128) {
        const int kp = idx >> 4, r = idx & 15;
        const int jjw = r >> 2, gw = r & 3;
        const float2 wv = *(const float2*)(whh + (size_t)((gw << 8) + j0 + jjw) * NHH + kp * 2);
        w2_s[idx] = pack2(wv.x, wv.y);
    }

    const int b  = tid >> 2;
    const int jj = tid & 3;
    float c_reg = 0.f;
    int* const flag_dir  = g_flags + dir * (NS * 64 * 8);
    int* const round_dir = g_round + dir * (NS * 8);
    const size_t hx_dir = (size_t)dir * NS * 64 * 128;
    const float* const gdir = g_gates + (size_t)dir * (NS * NB * NGATE) + j0 + jj;

    // prefetch gates for t=0
    float n_i, n_f, n_g, n_o;
    {
        const int s0 = dir ? (NS - 1) : 0;
        const float* gp = gdir + ((size_t)s0 * NB + b) * NGATE;
        n_i = __ldcg(gp); n_f = __ldcg(gp + 256); n_g = __ldcg(gp + 512); n_o = __ldcg(gp + 768);
    }
    __syncthreads();

    for (int t = 0; t < NS; t++) {
        const int s = dir ? (NS - 1 - t) : t;
        float a_i = n_i, a_f = n_f, a_g = n_g, a_o = n_o;
        // prefetch gates for t+1 (hide DRAM latency/jitter behind this step)
        if (t + 1 < NS) {
            const int sn = dir ? (s - 1) : (s + 1);
            const float* gp = gdir + ((size_t)sn * NB + b) * NGATE;
            n_i = __ldcg(gp); n_f = __ldcg(gp + 256); n_g = __ldcg(gp + 512); n_o = __ldcg(gp + 768);
        }

        if (t > 0) {
            const int sp = dir ? (s + 1) : (s - 1);
            if (cta == 0) {
                // aggregator: 64 threads each poll one producer flag
                if (tid < 64) {
                    const int* fp = flag_dir + sp * (64 * 8) + tid * 8;
                    while (ld_acquire_gpu(fp) == 0) {}
                }
                __syncthreads();
                if (tid == 0) st_release_gpu(round_dir + sp * 8, 1);
            } else {
                if (tid == 0) {
                    const int* rp = round_dir + sp * 8;
                    while (ld_acquire_gpu(rp) == 0) {}
                }
                __syncthreads();
            }
            // bulk coalesced stage of h_{t-1}: 32KB, 16 float4/thread, MLP 16
            const float4* src = (const float4*)(g_hx + hx_dir + (size_t)sp * 8192);
            float4* dst = (float4*)h_s;
#pragma unroll
            for (int i = 0; i < 16; i++) dst[tid + i * 128] = __ldcg(src + tid + i * 128);
            __syncthreads();

            ull acc0 = 0, acc1 = 0, acc2 = 0, acc3 = 0;
#pragma unroll 4
            for (int c = 0; c < 64; c++) {
                const ulonglong2 hv = *(const ulonglong2*)(h_s + c * 128 + b * 4);
                const ulonglong2 wa = *(const ulonglong2*)(w2_s + (2 * c) * 16 + jj * 4);
                const ulonglong2 wb = *(const ulonglong2*)(w2_s + (2 * c) * 16 + jj * 4 + 2);
                const ulonglong2 wc = *(const ulonglong2*)(w2_s + (2 * c + 1) * 16 + jj * 4);
                const ulonglong2 wd = *(const ulonglong2*)(w2_s + (2 * c + 1) * 16 + jj * 4 + 2);
                ffma2(acc0, hv.x, wa.x); ffma2(acc1, hv.x, wa.y);
                ffma2(acc2, hv.x, wb.x); ffma2(acc3, hv.x, wb.y);
                ffma2(acc0, hv.y, wc.x); ffma2(acc1, hv.y, wc.y);
                ffma2(acc2, hv.y, wd.x); ffma2(acc3, hv.y, wd.y);
            }
            const float2 r0 = unpack2(acc0), r1 = unpack2(acc1);
            const float2 r2 = unpack2(acc2), r3 = unpack2(acc3);
            a_i += r0.x + r0.y; a_f += r1.x + r1.y;
            a_g += r2.x + r2.y; a_o += r3.x + r3.y;
        }

        const float ig = sigf(a_i), fg = sigf(a_f), og = sigf(a_o);
        const float tg = 2.f * sigf(2.f * a_g) - 1.f;             // tanh
        const float cn = fg * c_reg + ig * tg;
        const float hn = og * (2.f * sigf(2.f * cn) - 1.f);
        c_reg = cn;
        __stcg(g_hx + hx_dir + ((size_t)s * 64 + cta) * 128 + tid, hn);  // coalesced 512B/CTA
        __syncthreads();
        if (tid == 0) st_release_gpu(flag_dir + s * (64 * 8) + cta * 8, 1);
    }
}

// ---------------- Phase C1: feats = hs @ fc_w^T + fc_b (reads chunk-major g_hx) ----------------
__global__ void feats_kernel(const float* __restrict__ fc_w,
                             const float* __restrict__ fc_b) {
    __shared__ float fcw_s[NT * 512];
    __shared__ float fcb_s[NT];
    const int s = blockIdx.x;
    const int tid = threadIdx.x;
    for (int i = tid; i < NT * 512; i += 256) fcw_s[i] = fc_w[i];
    if (tid < NT) fcb_s[tid] = fc_b[tid];
    __syncthreads();

    const int w = tid >> 5, lane = tid & 31;
    const float* base_f = g_hx + (size_t)s * 64 * 128;            // dir 0
    const float* base_b = g_hx + ((size_t)NS + s) * 64 * 128;     // dir 1
#pragma unroll
    for (int rep = 0; rep < 4; rep++) {
        const int b = w + rep * 8;
        const float4 v0 = __ldcg((const float4*)(base_f + (size_t)lane * 128 + b * 4));
        const float4 v1 = __ldcg((const float4*)(base_f + (size_t)(lane + 32) * 128 + b * 4));
        const float4 v2 = __ldcg((const float4*)(base_b + (size_t)lane * 128 + b * 4));
        const float4 v3 = __ldcg((const float4*)(base_b + (size_t)(lane + 32) * 128 + b * 4));
#pragma unroll
        for (int tt = 0; tt < NT; tt++) {
            const float4* wr = (const float4*)(fcw_s + tt * 512);
            const float4 w0 = wr[lane];
            const float4 w1 = wr[lane + 32];
            const float4 w2 = wr[lane + 64];
            const float4 w3 = wr[lane + 96];
            float p = v0.x * w0.x + v0.y * w0.y + v0.z * w0.z + v0.w * w0.w
                    + v1.x * w1.x + v1.y * w1.y + v1.z * w1.z + v1.w * w1.w
                    + v2.x * w2.x + v2.y * w2.y + v2.z * w2.z + v2.w * w2.w
                    + v3.x * w3.x + v3.y * w3.y + v3.z * w3.z + v3.w * w3.w;
            p += __shfl_xor_sync(0xffffffffu, p, 16);
            p += __shfl_xor_sync(0xffffffffu, p, 8);
            p += __shfl_xor_sync(0xffffffffu, p, 4);
            p += __shfl_xor_sync(0xffffffffu, p, 2);
            p += __shfl_xor_sync(0xffffffffu, p, 1);
            if (lane == 0) g_feat[((size_t)b * NS + s) * NT + tt] = p + fcb_s[tt];
        }
    }
}

// ---------------- Phase C2: Viterbi, one warp per batch ----------------
__global__ void viterbi_kernel(const float* __restrict__ trans,
                               float* __restrict__ out, int out_size) {
    __shared__ float feat_s[NS * NT];
    __shared__ unsigned char bp_s[NS * NT];
    __shared__ float term_s[NT];
    const int b = blockIdx.x;
    const int lane = threadIdx.x;  // 32

    const float4* src = (const float4*)(g_feat + (size_t)b * NS * NT);
    float4* dst = (float4*)feat_s;
    for (int i = lane; i < (NS * NT) / 4; i += 32) dst[i] = __ldcg(src + i);

    const int tl = (lane < NT) ? lane : (NT - 1);
    float tr_reg[NT];
#pragma unroll
    for (int p = 0; p < NT; p++) tr_reg[p] = trans[p * NT + tl];
    const float tr_stop = trans[tl * NT + TAG_STOP];
    __syncwarp();

    float v = (lane == TAG_START) ? 0.f : FNEG;
    for (int s = 0; s < NS; s++) {
        float best = -3.0e38f;
        int bpi = 0;
#pragma unroll
        for (int p = 0; p < NT; p++) {
            const float sc = __shfl_sync(0xffffffffu, v, p) + tr_reg[p];
            if (sc > best) { best = sc; bpi = p; }
        }
        v = best + feat_s[s * NT + tl];
        if (lane < NT) bp_s[s * NT + lane] = (unsigned char)bpi;
    }
    if (lane < NT) term_s[lane] = v + tr_stop;
    __syncwarp();
    if (lane == 0) {
        float best = term_s[0];
        int last = 0;
#pragma unroll
        for (int tt = 1; tt < NT; tt++)
            if (term_s[tt] > best) { best = term_s[tt]; last = tt; }
        if (b < out_size) out[b] = best;
        const int base = NB + b * NS;
        if (base + NS - 1 < out_size) out[base + NS - 1] = (float)last;
        int tag = last;
        for (int s = NS - 1; s >= 0; s--) {
            const int pv = bp_s[s * NT + tag];
            if (s >= 1 && base + s - 1 < out_size) out[base + s - 1] = (float)pv;
            tag = pv;
        }
    }
}

// ---------------- launch ----------------
extern "C" void kernel_launch(void* const* d_in, const int* in_sizes, int n_in,
                              void* d_out, int out_size) {
    const int*   inputs = (const int*)d_in[0];
    const float* embed  = (const float*)d_in[1];
    const float* wih_f  = (const float*)d_in[2];
    const float* whh_f  = (const float*)d_in[3];
    const float* bih_f  = (const float*)d_in[4];
    const float* bhh_f  = (const float*)d_in[5];
    const float* wih_b  = (const float*)d_in[6];
    const float* whh_b  = (const float*)d_in[7];
    const float* bih_b  = (const float*)d_in[8];
    const float* bhh_b  = (const float*)d_in[9];
    const float* fc_w   = (const float*)d_in[10];
    const float* fc_b   = (const float*)d_in[11];
    const float* trans  = (const float*)d_in[12];

    const int lstm_smem = 16384 + 32768;   // 48KB
    cudaFuncSetAttribute(lstm_rec_kernel, cudaFuncAttributeMaxDynamicSharedMemorySize, lstm_smem);

    zero_flags_kernel<<<256, 256>>>();
    input_gemm_kernel<<<dim3(16, 128, 2), 256>>>(inputs, embed,
                                                 wih_f, bih_f, bhh_f,
                                                 wih_b, bih_b, bhh_b);
    lstm_rec_kernel<<<128, 128, lstm_smem>>>(whh_f, whh_b);
    feats_kernel<<<NS, 256>>>(fc_w, fc_b);
    viterbi_kernel<<<NB, 32>>>(trans, (float*)d_out, out_size);
}

// round 6
// speedup vs baseline: 1.4306x; 1.4223x over previous
#include <cuda_runtime.h>
#include <cstdint>
#include <math.h>

typedef unsigned long long ull;

#define NB 32
#define NS 512
#define NE 300
#define NHH 256
#define NT 12
#define NGATE 1024
#define TAG_START 10
#define TAG_STOP 11
#define FNEG (-10000.0f)

// ---------------- scratch (static device arrays; no allocation) ----------------
static __device__ float g_gates[2u * NS * NB * NGATE];   // [dir][m=s*32+b][1024]
static __device__ float g_h[2u * NS * NB * NHH];         // [dir][s][b][256]
static __device__ float g_feat[(size_t)NB * NS * NT];    // [b][s][12]
static __device__ int   g_done[2u * NS * 32];            // [dir][s] stride-32 (128B lines)

__device__ __forceinline__ float sigf(float x) { return 1.f / (1.f + __expf(-x)); }

__device__ __forceinline__ ull pack2(float lo, float hi) {
    ull r; asm("mov.b64 %0, {%1, %2};" : "=l"(r) : "f"(lo), "f"(hi)); return r;
}
__device__ __forceinline__ float2 unpack2(ull v) {
    float2 f; asm("mov.b64 {%0, %1}, %2;" : "=f"(f.x), "=f"(f.y) : "l"(v)); return f;
}
__device__ __forceinline__ void ffma2(ull& d, ull a, ull b) {
    asm("fma.rn.f32x2 %0, %1, %2, %0;" : "+l"(d) : "l"(a), "l"(b));
}
__device__ __forceinline__ void red_release_add(int* p, int v) {
    asm volatile("red.release.gpu.global.add.u32 [%0], %1;" :: "l"(p), "r"(v) : "memory");
}
__device__ __forceinline__ int ld_acquire_gpu(const int* p) {
    int v; asm volatile("ld.acquire.gpu.global.b32 %0, [%1];" : "=r"(v) : "l"(p) : "memory");
    return v;
}

// ---------------- zero the counters (runs first each replay) ----------------
__global__ void zero_done_kernel() {
    const int n = 2 * NS * 32;
    for (int i = blockIdx.x * blockDim.x + threadIdx.x; i < n; i += gridDim.x * blockDim.x)
        g_done[i] = 0;
}

// ---------------- Phase A: embedding gather + input GEMM (f32x2) ----------------
// BM=128, BN=64, BK=20. 256 threads, 8x4 microtile, k-paired accumulators.
__global__ void __launch_bounds__(256)
input_gemm_kernel(const int* __restrict__ inputs,
                  const float* __restrict__ embed,
                  const float* __restrict__ wih_f,
                  const float* __restrict__ bih_f,
                  const float* __restrict__ bhh_f,
                  const float* __restrict__ wih_b,
                  const float* __restrict__ bih_b,
                  const float* __restrict__ bhh_b) {
    const int dir = blockIdx.z;
    const float* __restrict__ wih = dir ? wih_b : wih_f;
    const float* __restrict__ bih = dir ? bih_b : bih_f;
    const float* __restrict__ bhh = dir ? bhh_b : bhh_f;
    const int n0 = blockIdx.x * 64;
    const int m0 = blockIdx.y * 128;

    __shared__ int    tok_s[128];
    __shared__ float2 A_s[10 * 128];   // [kp][m] pairs (even k, odd k)
    __shared__ float2 W_s[10 * 64];    // [kp][n]

    const int tid = threadIdx.x;
    if (tid < 128) {
        const int m = m0 + tid;
        tok_s[tid] = inputs[(m & 31) * NS + (m >> 5)];
    }
    const int tn = tid & 15;
    const int tm = tid >> 4;

    ull acc[8][4];
#pragma unroll
    for (int i = 0; i < 8; i++)
#pragma unroll
        for (int j = 0; j < 4; j++) acc[i][j] = 0ull;

    __syncthreads();
    for (int kt = 0; kt < 15; kt++) {
        const int k0 = kt * 20;
        __syncthreads();
        for (int u = tid; u < 960; u += 256) {
            if (u < 640) {
                const int row = u / 5, c4 = u % 5;
                const float4 v = *(const float4*)(embed + (size_t)tok_s[row] * NE + k0 + c4 * 4);
                A_s[(c4 * 2) * 128 + row]     = make_float2(v.x, v.y);
                A_s[(c4 * 2 + 1) * 128 + row] = make_float2(v.z, v.w);
            } else {
                const int idx = u - 640;
                const int n = idx / 5, c4 = idx % 5;
                const float4 v = *(const float4*)(wih + (size_t)(n0 + n) * NE + k0 + c4 * 4);
                W_s[(c4 * 2) * 64 + n]     = make_float2(v.x, v.y);
                W_s[(c4 * 2 + 1) * 64 + n] = make_float2(v.z, v.w);
            }
        }
        __syncthreads();
#pragma unroll
        for (int kp = 0; kp < 10; kp++) {
            const ulonglong2* ap = (const ulonglong2*)(A_s + kp * 128 + tm * 8);
            const ulonglong2* wp = (const ulonglong2*)(W_s + kp * 64 + tn * 4);
            const ulonglong2 a0 = ap[0], a1 = ap[1], a2 = ap[2], a3 = ap[3];
            const ulonglong2 w0 = wp[0], w1 = wp[1];
            const ull a[8] = {a0.x, a0.y, a1.x, a1.y, a2.x, a2.y, a3.x, a3.y};
            const ull w[4] = {w0.x, w0.y, w1.x, w1.y};
#pragma unroll
            for (int i = 0; i < 8; i++)
#pragma unroll
                for (int j = 0; j < 4; j++) ffma2(acc[i][j], a[i], w[j]);
        }
    }

    const int ncol = n0 + tn * 4;
    const float4 b1 = *(const float4*)(bih + ncol);
    const float4 b2 = *(const float4*)(bhh + ncol);
    const float bx = b1.x + b2.x, by = b1.y + b2.y, bz = b1.z + b2.z, bw = b1.w + b2.w;
#pragma unroll
    for (int i = 0; i < 8; i++) {
        const int m = m0 + tm * 8 + i;
        const float2 s0 = unpack2(acc[i][0]);
        const float2 s1 = unpack2(acc[i][1]);
        const float2 s2 = unpack2(acc[i][2]);
        const float2 s3 = unpack2(acc[i][3]);
        const float4 o = make_float4(s0.x + s0.y + bx, s1.x + s1.y + by,
                                     s2.x + s2.y + bz, s3.x + s3.y + bw);
        *(float4*)(g_gates + ((size_t)dir * (NS * NB) + m) * NGATE + ncol) = o;
    }
}

// ---------------- Phase B: persistent bidirectional LSTM recurrence (f32x2) ----------------
// 128 CTAs (dir = bx>>6, cta = bx&63), 128 threads. CTA owns hidden units [cta*4, cta*4+4).
// R2 skeleton (k-split + p_s reduction) with: XOR-swizzled h_s (conflict-free),
// gate-input prefetch one step ahead, red.release arrival (no threadfence), fast tanh.
__global__ void lstm_rec_kernel(const float* __restrict__ whh_f,
                                const float* __restrict__ whh_b) {
    extern __shared__ char smraw[];
    ull*   w2_s = (ull*)smraw;                    // [kp=128][r=16] = 16KB
    float* h_s  = (float*)(smraw + 16384);        // [b=32][256] XOR-swizzled = 32KB
    ull*   p_s  = (ull*)(smraw + 49152);          // [ks=4][b=32][18] = 18KB

    const int tid = threadIdx.x;
    const int dir = blockIdx.x >> 6;
    const int cta = blockIdx.x & 63;
    const int j0 = cta * 4;
    const float* __restrict__ whh = dir ? whh_b : whh_f;

    // repack whh rows for this CTA as (even-k, odd-k) pairs: w2_s[kp*16 + r], r = g*4+jj
    for (int idx = tid; idx < 2048; idx += 128) {
        const int kp = idx >> 4, r = idx & 15;
        const int row = (r >> 2) * NHH + j0 + (r & 3);
        const float2 wv = *(const float2*)(whh + (size_t)row * NHH + kp * 2);
        w2_s[idx] = pack2(wv.x, wv.y);
    }

    const int lane = tid & 31;
    const int ks = tid >> 5;
    const int b4 = lane >> 2, r4 = lane & 3;
    const int bb = tid >> 2, jj = tid & 3;
    float c_reg = 0.f;
    const size_t hb_dir = (size_t)dir * NS * NB * NHH;
    int* const done_dir = g_done + dir * (NS * 32);
    const float* const gdir = g_gates + (size_t)dir * (NS * NB * NGATE) + j0 + jj;

    // prefetch gates for t=0
    float n_i, n_f, n_g, n_o;
    {
        const int s0 = dir ? (NS - 1) : 0;
        const float* gp = gdir + ((size_t)s0 * NB + bb) * NGATE;
        n_i = __ldcg(gp); n_f = __ldcg(gp + 256); n_g = __ldcg(gp + 512); n_o = __ldcg(gp + 768);
    }
    __syncthreads();

    for (int t = 0; t < NS; t++) {
        const int s = dir ? (NS - 1 - t) : t;
        float a_i = n_i, a_f = n_f, a_g = n_g, a_o = n_o;
        // prefetch gates for t+1 (hide DRAM latency behind this whole step)
        if (t + 1 < NS) {
            const int sn = dir ? (s - 1) : (s + 1);
            const float* gp = gdir + ((size_t)sn * NB + bb) * NGATE;
            n_i = __ldcg(gp); n_f = __ldcg(gp + 256); n_g = __ldcg(gp + 512); n_o = __ldcg(gp + 768);
        }

        if (t > 0) {
            const int sp = dir ? (s + 1) : (s - 1);
            if (tid == 0) {
                const int* dp = done_dir + sp * 32;
                while (ld_acquire_gpu(dp) < 64) {}
            }
            __syncthreads();
            // stage h_{t-1} into swizzled smem: dst = b*256 + ((f ^ (b>>2)) * 4)
            const float4* src = (const float4*)(g_h + hb_dir + (size_t)sp * (NB * NHH));
#pragma unroll
            for (int i = 0; i < 16; i++) {
                const int lin = tid + i * 128;
                const int b = lin >> 6, f = lin & 63;
                *(float4*)(h_s + b * 256 + ((f ^ (b >> 2)) << 2)) = __ldcg(src + lin);
            }
            __syncthreads();

            ull acc[4][4];
#pragma unroll
            for (int bi = 0; bi < 4; bi++) {
                acc[bi][0] = 0ull; acc[bi][1] = 0ull; acc[bi][2] = 0ull; acc[bi][3] = 0ull;
            }
            const int fbase = ks * 16;   // float4 index base in h row
#pragma unroll 4
            for (int kk = 0; kk < 16; kk++) {
                const int f = fbase + kk;
                const int kp0 = f << 1;
                const ulonglong2 wa = *(const ulonglong2*)(w2_s + kp0 * 16 + r4 * 4);
                const ulonglong2 wb = *(const ulonglong2*)(w2_s + kp0 * 16 + r4 * 4 + 2);
                const ulonglong2 wc = *(const ulonglong2*)(w2_s + (kp0 + 1) * 16 + r4 * 4);
                const ulonglong2 wd = *(const ulonglong2*)(w2_s + (kp0 + 1) * 16 + r4 * 4 + 2);
#pragma unroll
                for (int bi = 0; bi < 4; bi++) {
                    const int b = b4 * 4 + bi;
                    const float4 hf = *(const float4*)(h_s + b * 256 + ((f ^ b4) << 2));
                    const ull hx = pack2(hf.x, hf.y);
                    const ull hy = pack2(hf.z, hf.w);
                    ffma2(acc[bi][0], hx, wa.x);
                    ffma2(acc[bi][1], hx, wa.y);
                    ffma2(acc[bi][2], hx, wb.x);
                    ffma2(acc[bi][3], hx, wb.y);
                    ffma2(acc[bi][0], hy, wc.x);
                    ffma2(acc[bi][1], hy, wc.y);
                    ffma2(acc[bi][2], hy, wd.x);
                    ffma2(acc[bi][3], hy, wd.y);
                }
            }
#pragma unroll
            for (int bi = 0; bi < 4; bi++) {
                ull* pp = p_s + ks * 576 + (b4 * 4 + bi) * 18 + r4 * 4;
                *(ulonglong2*)pp       = make_ulonglong2(acc[bi][0], acc[bi][1]);
                *(ulonglong2*)(pp + 2) = make_ulonglong2(acc[bi][2], acc[bi][3]);
            }
            __syncthreads();
            // reduce 4 k-quarters x 2 packed lanes per gate
            const float2* pf = (const float2*)p_s;
#pragma unroll
            for (int q = 0; q < 4; q++) {
                const int base = q * 576 + bb * 18 + jj;
                const float2 v0 = pf[base + 0];
                const float2 v1 = pf[base + 4];
                const float2 v2 = pf[base + 8];
                const float2 v3 = pf[base + 12];
                a_i += v0.x + v0.y;
                a_f += v1.x + v1.y;
                a_g += v2.x + v2.y;
                a_o += v3.x + v3.y;
            }
        }
        const float ig = sigf(a_i), fg = sigf(a_f), og = sigf(a_o);
        const float tg = 2.f * sigf(2.f * a_g) - 1.f;             // tanh
        const float cn = fg * c_reg + ig * tg;
        const float hn = og * (2.f * sigf(2.f * cn) - 1.f);
        c_reg = cn;
        __stcg(g_h + hb_dir + ((size_t)s * NB + bb) * NHH + j0 + jj, hn);
        __syncthreads();
        if (tid == 0) red_release_add(done_dir + s * 32, 1);
    }
}

// ---------------- Phase C1: feats = hs @ fc_w^T + fc_b (reads b-major g_h) ----------------
__global__ void feats_kernel(const float* __restrict__ fc_w,
                             const float* __restrict__ fc_b) {
    __shared__ float fcw_s[NT * 512];
    __shared__ float fcb_s[NT];
    const int s = blockIdx.x;
    const int tid = threadIdx.x;
    for (int i = tid; i < NT * 512; i += 256) fcw_s[i] = fc_w[i];
    if (tid < NT) fcb_s[tid] = fc_b[tid];
    __syncthreads();

    const int w = tid >> 5, lane = tid & 31;
#pragma unroll
    for (int rep = 0; rep < 4; rep++) {
        const int b = w + rep * 8;
        const float4* hf = (const float4*)(g_h + ((size_t)s * NB + b) * NHH);
        const float4* hb = (const float4*)(g_h + (size_t)NS * NB * NHH + ((size_t)s * NB + b) * NHH);
        const float4 v0 = __ldcg(hf + lane);
        const float4 v1 = __ldcg(hf + lane + 32);
        const float4 v2 = __ldcg(hb + lane);
        const float4 v3 = __ldcg(hb + lane + 32);
#pragma unroll
        for (int tt = 0; tt < NT; tt++) {
            const float4* wr = (const float4*)(fcw_s + tt * 512);
            const float4 w0 = wr[lane];
            const float4 w1 = wr[lane + 32];
            const float4 w2 = wr[lane + 64];
            const float4 w3 = wr[lane + 96];
            float p = v0.x * w0.x + v0.y * w0.y + v0.z * w0.z + v0.w * w0.w
                    + v1.x * w1.x + v1.y * w1.y + v1.z * w1.z + v1.w * w1.w
                    + v2.x * w2.x + v2.y * w2.y + v2.z * w2.z + v2.w * w2.w
                    + v3.x * w3.x + v3.y * w3.y + v3.z * w3.z + v3.w * w3.w;
            p += __shfl_xor_sync(0xffffffffu, p, 16);
            p += __shfl_xor_sync(0xffffffffu, p, 8);
            p += __shfl_xor_sync(0xffffffffu, p, 4);
            p += __shfl_xor_sync(0xffffffffu, p, 2);
            p += __shfl_xor_sync(0xffffffffu, p, 1);
            if (lane == 0) g_feat[((size_t)b * NS + s) * NT + tt] = p + fcb_s[tt];
        }
    }
}

// ---------------- Phase C2: Viterbi, one warp per batch ----------------
__global__ void viterbi_kernel(const float* __restrict__ trans,
                               float* __restrict__ out, int out_size) {
    __shared__ float feat_s[NS * NT];
    __shared__ unsigned char bp_s[NS * NT];
    __shared__ float term_s[NT];
    const int b = blockIdx.x;
    const int lane = threadIdx.x;  // 32

    const float4* src = (const float4*)(g_feat + (size_t)b * NS * NT);
    float4* dst = (float4*)feat_s;
    for (int i = lane; i < (NS * NT) / 4; i += 32) dst[i] = __ldcg(src + i);

    const int tl = (lane < NT) ? lane : (NT - 1);
    float tr_reg[NT];
#pragma unroll
    for (int p = 0; p < NT; p++) tr_reg[p] = trans[p * NT + tl];
    const float tr_stop = trans[tl * NT + TAG_STOP];
    __syncwarp();

    float v = (lane == TAG_START) ? 0.f : FNEG;
    for (int s = 0; s < NS; s++) {
        float best = -3.0e38f;
        int bpi = 0;
#pragma unroll
        for (int p = 0; p < NT; p++) {
            const float sc = __shfl_sync(0xffffffffu, v, p) + tr_reg[p];
            if (sc > best) { best = sc; bpi = p; }
        }
        v = best + feat_s[s * NT + tl];
        if (lane < NT) bp_s[s * NT + lane] = (unsigned char)bpi;
    }
    if (lane < NT) term_s[lane] = v + tr_stop;
    __syncwarp();
    if (lane == 0) {
        float best = term_s[0];
        int last = 0;
#pragma unroll
        for (int tt = 1; tt < NT; tt++)
            if (term_s[tt] > best) { best = term_s[tt]; last = tt; }
        if (b < out_size) out[b] = best;
        const int base = NB + b * NS;
        if (base + NS - 1 < out_size) out[base + NS - 1] = (float)last;
        int tag = last;
        for (int s = NS - 1; s >= 0; s--) {
            const int pv = bp_s[s * NT + tag];
            if (s >= 1 && base + s - 1 < out_size) out[base + s - 1] = (float)pv;
            tag = pv;
        }
    }
}

// ---------------- launch ----------------
extern "C" void kernel_launch(void* const* d_in, const int* in_sizes, int n_in,
                              void* d_out, int out_size) {
    const int*   inputs = (const int*)d_in[0];
    const float* embed  = (const float*)d_in[1];
    const float* wih_f  = (const float*)d_in[2];
    const float* whh_f  = (const float*)d_in[3];
    const float* bih_f  = (const float*)d_in[4];
    const float* bhh_f  = (const float*)d_in[5];
    const float* wih_b  = (const float*)d_in[6];
    const float* whh_b  = (const float*)d_in[7];
    const float* bih_b  = (const float*)d_in[8];
    const float* bhh_b  = (const float*)d_in[9];
    const float* fc_w   = (const float*)d_in[10];
    const float* fc_b   = (const float*)d_in[11];
    const float* trans  = (const float*)d_in[12];

    const int lstm_smem = 16384 + 32768 + 18432;   // 67584 bytes
    cudaFuncSetAttribute(lstm_rec_kernel, cudaFuncAttributeMaxDynamicSharedMemorySize, lstm_smem);

    zero_done_kernel<<<128, 256>>>();
    input_gemm_kernel<<<dim3(16, 128, 2), 256>>>(inputs, embed,
                                                 wih_f, bih_f, bhh_f,
                                                 wih_b, bih_b, bhh_b);
    lstm_rec_kernel<<<128, 128, lstm_smem>>>(whh_f, whh_b);
    feats_kernel<<<NS, 256>>>(fc_w, fc_b);
    viterbi_kernel<<<NB, 32>>>(trans, (float*)d_out, out_size);
}